// round 1
// baseline (speedup 1.0000x reference)
#include <cuda_runtime.h>
#include <cstdint>
#include <math.h>

// Problem dims
#define BSZ 256
#define TT  64
#define AA  32
#define HH  512
#define EE  32

// Scratch (allocation-free: device globals)
__device__ float g_h1[BSZ * TT * HH];   // layer-1 output (B,T,H)
__device__ float g_x2[BSZ * TT * HH];   // layer-2 output (B,T,H)
__device__ float g_tc[BSZ * HH];        // tau contribution per sample (B,H)

// ---------------------------------------------------------------------------
// Kernel 1: per-sample, 256 threads.
//   h1 = actions @ W1[e] + b1          (64x32)@(32x512)
//   tau = sinusoidal(t, 512)
//   tc  = tau @ W2[e][512:1024, :]     (512-matvec)
// ---------------------------------------------------------------------------
__global__ __launch_bounds__(256) void k1_embed(
    const float* __restrict__ actions,   // (B,T,A)
    const int*   __restrict__ timesteps, // (B,)
    const int*   __restrict__ cat_ids,   // (B,)
    const float* __restrict__ W1,        // (E,A,H)
    const float* __restrict__ b1,        // (E,H)
    const float* __restrict__ W2)        // (E,2H,H)
{
    const int b   = blockIdx.x;
    const int tid = threadIdx.x;
    const int e   = cat_ids[b];
    const float tval = (float)timesteps[b];

    __shared__ float sA[TT][36];     // actions tile, padded (36*4 bytes = 16B-aligned rows)
    __shared__ float stau[HH];

    // load actions (64x32) -> smem, vectorized
    const float* Ab = actions + (size_t)b * TT * AA;
    #pragma unroll
    for (int i = 0; i < 2; i++) {
        int id  = tid + i * 256;
        int row = id >> 3;           // 0..63
        int c4  = id & 7;            // 0..7
        float4 v = *reinterpret_cast<const float4*>(&Ab[row * AA + c4 * 4]);
        *reinterpret_cast<float4*>(&sA[row][c4 * 4]) = v;
    }

    // sinusoidal embedding: half = 256, exactly one freq per thread
    {
        float expo = -(float)tid * (9.210340371976184f / 256.0f); // ln(1e4)/half
        float f = tval * expf(expo);
        stau[tid]       = sinf(f);
        stau[256 + tid] = cosf(f);
    }
    __syncthreads();

    // each thread owns 2 output columns h0, h1
    const int h0 = tid;
    const int h1c = tid + 256;

    const float* W1e = W1 + (size_t)e * AA * HH;
    float w0[AA], w1[AA];
    #pragma unroll
    for (int k = 0; k < AA; k++) {
        w0[k] = W1e[k * HH + h0];
        w1[k] = W1e[k * HH + h1c];
    }
    const float bias0 = b1[e * HH + h0];
    const float bias1 = b1[e * HH + h1c];

    float* H1b = g_h1 + (size_t)b * TT * HH;
    for (int t = 0; t < TT; t++) {
        float acc0 = bias0, acc1 = bias1;
        #pragma unroll
        for (int k4 = 0; k4 < 8; k4++) {
            float4 a = *reinterpret_cast<const float4*>(&sA[t][k4 * 4]);
            acc0 += a.x * w0[k4 * 4 + 0]; acc1 += a.x * w1[k4 * 4 + 0];
            acc0 += a.y * w0[k4 * 4 + 1]; acc1 += a.y * w1[k4 * 4 + 1];
            acc0 += a.z * w0[k4 * 4 + 2]; acc1 += a.z * w1[k4 * 4 + 2];
            acc0 += a.w * w0[k4 * 4 + 3]; acc1 += a.w * w1[k4 * 4 + 3];
        }
        H1b[t * HH + h0]  = acc0;
        H1b[t * HH + h1c] = acc1;
    }

    // tau contribution: tc[h] = sum_k tau[k] * W2[e][512+k][h]
    const float* W2tau = W2 + (size_t)e * (2 * HH) * HH + (size_t)HH * HH;
    float acc0 = 0.f, acc1 = 0.f;
    #pragma unroll 8
    for (int k = 0; k < HH; k++) {
        float tk = stau[k];
        acc0 += tk * W2tau[k * HH + h0];
        acc1 += tk * W2tau[k * HH + h1c];
    }
    g_tc[b * HH + h0]  = acc0;
    g_tc[b * HH + h1c] = acc1;
}

// ---------------------------------------------------------------------------
// Tiled GEMM per sample: C(64,512) = A(64,512) @ W[e](512,512) + bias (+tc) [+swish]
// CTA tile 64x128, K-tile 32, 256 threads, thread tile 4(M) x 8(N).
// Inner product uses packed fma.rn.f32x2 (N-paired accumulators).
// LAYER==2: A=g_h1, C=g_x2, swish epilogue with tc.  LAYER==3: A=g_x2, C=out.
// ---------------------------------------------------------------------------
#define FMA2(d, a, bb) asm("fma.rn.f32x2 %0, %1, %2, %0;" : "+l"(d) : "l"(a), "l"(bb))
#define PACKDUP(d, f)  { unsigned _r = __float_as_uint(f); \
                         asm("mov.b64 %0, {%1, %1};" : "=l"(d) : "r"(_r)); }
#define UNPACK2(lo, hi, v) asm("mov.b64 {%0, %1}, %2;" : "=r"(lo), "=r"(hi) : "l"(v))

template <int LAYER>
__global__ __launch_bounds__(256, 2) void gemm64(
    const float* __restrict__ W,       // (E, Krows, H)
    const float* __restrict__ bias,    // (E, H)
    const int*   __restrict__ cat_ids,
    float*       __restrict__ Cout)    // used for LAYER==3
{
    constexpr int BN = 128;
    constexpr int BK = 32;
    constexpr int NKT = HH / BK;       // 16
    constexpr int WROWS = (LAYER == 2) ? (2 * HH) : HH;

    const int b  = blockIdx.y;
    const int n0 = blockIdx.x * BN;
    const int e  = cat_ids[b];

    const float* A  = (LAYER == 2) ? g_h1 : g_x2;
    const float* Ab = A + (size_t)b * TT * HH;
    const float* Wb = W + (size_t)e * WROWS * HH;   // rows 0..511 of W2 are the a_emb half
    float* Cb = ((LAYER == 2) ? g_x2 : Cout) + (size_t)b * TT * HH;

    __shared__ float sAT[BK][68];   // [k][m], pad 68 (16B-aligned, conflict-free)
    __shared__ float sB[BK][BN];    // [k][n]

    const int tid   = threadIdx.x;
    const int a_row = tid & 63;     // M row for A loads
    const int a_c4  = tid >> 6;     // 0..3 (k-group)
    const int b_row = tid >> 5;     // 0..7 (k row for B loads)
    const int b_c4  = tid & 31;     // float4 col
    const int tm    = tid >> 4;     // 0..15 -> rows tm*4..+3
    const int tn    = tid & 15;     // 0..15 -> cols tn*8..+7

    unsigned long long acc[4][4];
    #pragma unroll
    for (int m = 0; m < 4; m++)
        #pragma unroll
        for (int j = 0; j < 4; j++) acc[m][j] = 0ull;

    // ---- load first K-tile directly to smem ----
    #pragma unroll
    for (int i = 0; i < 2; i++) {
        int c4 = a_c4 + i * 4;
        float4 v = *reinterpret_cast<const float4*>(&Ab[a_row * HH + c4 * 4]);
        sAT[c4 * 4 + 0][a_row] = v.x;
        sAT[c4 * 4 + 1][a_row] = v.y;
        sAT[c4 * 4 + 2][a_row] = v.z;
        sAT[c4 * 4 + 3][a_row] = v.w;
    }
    #pragma unroll
    for (int i = 0; i < 4; i++) {
        int r = b_row + i * 8;
        *reinterpret_cast<float4*>(&sB[r][b_c4 * 4]) =
            *reinterpret_cast<const float4*>(&Wb[r * HH + n0 + b_c4 * 4]);
    }
    __syncthreads();

    float4 pa[2], pb[4];

    for (int kt = 0; kt < NKT; kt++) {
        const int k0n = (kt + 1) * BK;
        const bool pre = (kt + 1 < NKT);
        if (pre) {
            #pragma unroll
            for (int i = 0; i < 2; i++) {
                int c4 = a_c4 + i * 4;
                pa[i] = *reinterpret_cast<const float4*>(&Ab[a_row * HH + k0n + c4 * 4]);
            }
            #pragma unroll
            for (int i = 0; i < 4; i++) {
                int r = b_row + i * 8;
                pb[i] = *reinterpret_cast<const float4*>(&Wb[(k0n + r) * HH + n0 + b_c4 * 4]);
            }
        }

        // ---- compute 32 k-steps ----
        #pragma unroll 8
        for (int k = 0; k < BK; k++) {
            float4 av = *reinterpret_cast<const float4*>(&sAT[k][tm * 4]);
            ulonglong2 b01 = *reinterpret_cast<const ulonglong2*>(&sB[k][tn * 8]);
            ulonglong2 b23 = *reinterpret_cast<const ulonglong2*>(&sB[k][tn * 8 + 4]);
            unsigned long long bb0 = b01.x, bb1 = b01.y, bb2 = b23.x, bb3 = b23.y;
            float am[4] = {av.x, av.y, av.z, av.w};
            #pragma unroll
            for (int m = 0; m < 4; m++) {
                unsigned long long a2;
                PACKDUP(a2, am[m]);
                FMA2(acc[m][0], a2, bb0);
                FMA2(acc[m][1], a2, bb1);
                FMA2(acc[m][2], a2, bb2);
                FMA2(acc[m][3], a2, bb3);
            }
        }
        __syncthreads();

        if (pre) {
            #pragma unroll
            for (int i = 0; i < 2; i++) {
                int c4 = a_c4 + i * 4;
                sAT[c4 * 4 + 0][a_row] = pa[i].x;
                sAT[c4 * 4 + 1][a_row] = pa[i].y;
                sAT[c4 * 4 + 2][a_row] = pa[i].z;
                sAT[c4 * 4 + 3][a_row] = pa[i].w;
            }
            #pragma unroll
            for (int i = 0; i < 4; i++) {
                int r = b_row + i * 8;
                *reinterpret_cast<float4*>(&sB[r][b_c4 * 4]) = pb[i];
            }
            __syncthreads();
        }
    }

    // ---- epilogue ----
    const float* biasE = bias + e * HH;
    const float* tcB   = g_tc + (size_t)b * HH;
    #pragma unroll
    for (int m = 0; m < 4; m++) {
        int row = tm * 4 + m;
        #pragma unroll
        for (int j = 0; j < 4; j++) {
            unsigned lo, hi;
            UNPACK2(lo, hi, acc[m][j]);
            int n = n0 + tn * 8 + j * 2;
            float v0 = __uint_as_float(lo) + biasE[n];
            float v1 = __uint_as_float(hi) + biasE[n + 1];
            if (LAYER == 2) {
                v0 += tcB[n];
                v1 += tcB[n + 1];
                v0 = v0 / (1.0f + expf(-v0));   // swish
                v1 = v1 / (1.0f + expf(-v1));
            }
            *reinterpret_cast<float2*>(&Cb[row * HH + n]) = make_float2(v0, v1);
        }
    }
}

// ---------------------------------------------------------------------------
extern "C" void kernel_launch(void* const* d_in, const int* in_sizes, int n_in,
                              void* d_out, int out_size)
{
    const float* actions   = (const float*)d_in[0];
    const int*   timesteps = (const int*)  d_in[1];
    const int*   cat_ids   = (const int*)  d_in[2];
    const float* W1        = (const float*)d_in[3];
    const float* b1        = (const float*)d_in[4];
    const float* W2        = (const float*)d_in[5];
    const float* b2        = (const float*)d_in[6];
    const float* W3        = (const float*)d_in[7];
    const float* b3        = (const float*)d_in[8];
    float* out = (float*)d_out;

    k1_embed<<<BSZ, 256>>>(actions, timesteps, cat_ids, W1, b1, W2);

    dim3 grid(HH / 128, BSZ);
    gemm64<2><<<grid, 256>>>(W2, b2, cat_ids, nullptr);  // -> g_x2 (swish, +tc)
    gemm64<3><<<grid, 256>>>(W3, b3, cat_ids, out);      // -> d_out
}

// round 2
// speedup vs baseline: 1.0038x; 1.0038x over previous
#include <cuda_runtime.h>
#include <cstdint>
#include <math.h>

// Problem dims
#define BSZ 256
#define TT  64
#define AA  32
#define HH  512
#define EE  32

// Scratch (allocation-free: device globals)
__device__ float g_h1[BSZ * TT * HH];   // layer-1 output (B,T,H)
__device__ float g_x2[BSZ * TT * HH];   // layer-2 output (B,T,H)
__device__ float g_tc[BSZ * HH];        // tau contribution per sample (B,H)

// ---------------------------------------------------------------------------
// Kernel 1: per-sample, 256 threads.
//   h1 = actions @ W1[e] + b1          (64x32)@(32x512)
//   tau = sinusoidal(t, 512)
//   tc  = tau @ W2[e][512:1024, :]     (512-matvec)
// ---------------------------------------------------------------------------
__global__ __launch_bounds__(256) void k1_embed(
    const float* __restrict__ actions,   // (B,T,A)
    const int*   __restrict__ timesteps, // (B,)
    const int*   __restrict__ cat_ids,   // (B,)
    const float* __restrict__ W1,        // (E,A,H)
    const float* __restrict__ b1,        // (E,H)
    const float* __restrict__ W2)        // (E,2H,H)
{
    const int b   = blockIdx.x;
    const int tid = threadIdx.x;
    const int e   = cat_ids[b];
    const float tval = (float)timesteps[b];

    __shared__ float sA[TT][36];     // actions tile, padded (36*4 bytes = 16B-aligned rows)
    __shared__ float stau[HH];

    // load actions (64x32) -> smem, vectorized
    const float* Ab = actions + (size_t)b * TT * AA;
    #pragma unroll
    for (int i = 0; i < 2; i++) {
        int id  = tid + i * 256;
        int row = id >> 3;           // 0..63
        int c4  = id & 7;            // 0..7
        float4 v = *reinterpret_cast<const float4*>(&Ab[row * AA + c4 * 4]);
        *reinterpret_cast<float4*>(&sA[row][c4 * 4]) = v;
    }

    // sinusoidal embedding: half = 256, exactly one freq per thread
    {
        float expo = -(float)tid * (9.210340371976184f / 256.0f); // ln(1e4)/half
        float f = tval * expf(expo);
        stau[tid]       = sinf(f);
        stau[256 + tid] = cosf(f);
    }
    __syncthreads();

    // each thread owns 2 output columns h0, h1
    const int h0 = tid;
    const int h1c = tid + 256;

    const float* W1e = W1 + (size_t)e * AA * HH;
    float w0[AA], w1[AA];
    #pragma unroll
    for (int k = 0; k < AA; k++) {
        w0[k] = W1e[k * HH + h0];
        w1[k] = W1e[k * HH + h1c];
    }
    const float bias0 = b1[e * HH + h0];
    const float bias1 = b1[e * HH + h1c];

    float* H1b = g_h1 + (size_t)b * TT * HH;
    for (int t = 0; t < TT; t++) {
        float acc0 = bias0, acc1 = bias1;
        #pragma unroll
        for (int k4 = 0; k4 < 8; k4++) {
            float4 a = *reinterpret_cast<const float4*>(&sA[t][k4 * 4]);
            acc0 += a.x * w0[k4 * 4 + 0]; acc1 += a.x * w1[k4 * 4 + 0];
            acc0 += a.y * w0[k4 * 4 + 1]; acc1 += a.y * w1[k4 * 4 + 1];
            acc0 += a.z * w0[k4 * 4 + 2]; acc1 += a.z * w1[k4 * 4 + 2];
            acc0 += a.w * w0[k4 * 4 + 3]; acc1 += a.w * w1[k4 * 4 + 3];
        }
        H1b[t * HH + h0]  = acc0;
        H1b[t * HH + h1c] = acc1;
    }

    // tau contribution: tc[h] = sum_k tau[k] * W2[e][512+k][h]
    const float* W2tau = W2 + (size_t)e * (2 * HH) * HH + (size_t)HH * HH;
    float acc0 = 0.f, acc1 = 0.f;
    #pragma unroll 8
    for (int k = 0; k < HH; k++) {
        float tk = stau[k];
        acc0 += tk * W2tau[k * HH + h0];
        acc1 += tk * W2tau[k * HH + h1c];
    }
    g_tc[b * HH + h0]  = acc0;
    g_tc[b * HH + h1c] = acc1;
}

// ---------------------------------------------------------------------------
// Tiled GEMM per sample: C(64,512) = A(64,512) @ W[e](512,512) + bias (+tc) [+swish]
// CTA tile 64x128, K-tile 32, 256 threads, thread tile 4(M) x 8(N).
// Inner product uses packed fma.rn.f32x2 (N-paired accumulators).
// LAYER==2: A=g_h1, C=g_x2, swish epilogue with tc.  LAYER==3: A=g_x2, C=out.
// ---------------------------------------------------------------------------
#define FMA2(d, a, bb) asm("fma.rn.f32x2 %0, %1, %2, %0;" : "+l"(d) : "l"(a), "l"(bb))
#define PACKDUP(d, f)  { unsigned _r = __float_as_uint(f); \
                         asm("mov.b64 %0, {%1, %1};" : "=l"(d) : "r"(_r)); }
#define UNPACK2(lo, hi, v) asm("mov.b64 {%0, %1}, %2;" : "=r"(lo), "=r"(hi) : "l"(v))

template <int LAYER>
__global__ __launch_bounds__(256, 2) void gemm64(
    const float* __restrict__ W,       // (E, Krows, H)
    const float* __restrict__ bias,    // (E, H)
    const int*   __restrict__ cat_ids,
    float*       __restrict__ Cout)    // used for LAYER==3
{
    constexpr int BN = 128;
    constexpr int BK = 32;
    constexpr int NKT = HH / BK;       // 16
    constexpr int WROWS = (LAYER == 2) ? (2 * HH) : HH;

    const int b  = blockIdx.y;
    const int n0 = blockIdx.x * BN;
    const int e  = cat_ids[b];

    const float* A  = (LAYER == 2) ? g_h1 : g_x2;
    const float* Ab = A + (size_t)b * TT * HH;
    const float* Wb = W + (size_t)e * WROWS * HH;   // rows 0..511 of W2 are the a_emb half
    float* Cb = ((LAYER == 2) ? g_x2 : Cout) + (size_t)b * TT * HH;

    __shared__ float sAT[BK][68];   // [k][m], pad 68 (16B-aligned, conflict-free)
    __shared__ float sB[BK][BN];    // [k][n]

    const int tid   = threadIdx.x;
    const int a_row = tid & 63;     // M row for A loads
    const int a_c4  = tid >> 6;     // 0..3 (k-group)
    const int b_row = tid >> 5;     // 0..7 (k row for B loads)
    const int b_c4  = tid & 31;     // float4 col
    const int tm    = tid >> 4;     // 0..15 -> rows tm*4..+3
    const int tn    = tid & 15;     // 0..15 -> cols tn*8..+7

    unsigned long long acc[4][4];
    #pragma unroll
    for (int m = 0; m < 4; m++)
        #pragma unroll
        for (int j = 0; j < 4; j++) acc[m][j] = 0ull;

    // ---- load first K-tile directly to smem ----
    #pragma unroll
    for (int i = 0; i < 2; i++) {
        int c4 = a_c4 + i * 4;
        float4 v = *reinterpret_cast<const float4*>(&Ab[a_row * HH + c4 * 4]);
        sAT[c4 * 4 + 0][a_row] = v.x;
        sAT[c4 * 4 + 1][a_row] = v.y;
        sAT[c4 * 4 + 2][a_row] = v.z;
        sAT[c4 * 4 + 3][a_row] = v.w;
    }
    #pragma unroll
    for (int i = 0; i < 4; i++) {
        int r = b_row + i * 8;
        *reinterpret_cast<float4*>(&sB[r][b_c4 * 4]) =
            *reinterpret_cast<const float4*>(&Wb[r * HH + n0 + b_c4 * 4]);
    }
    __syncthreads();

    float4 pa[2], pb[4];

    for (int kt = 0; kt < NKT; kt++) {
        const int k0n = (kt + 1) * BK;
        const bool pre = (kt + 1 < NKT);
        if (pre) {
            #pragma unroll
            for (int i = 0; i < 2; i++) {
                int c4 = a_c4 + i * 4;
                pa[i] = *reinterpret_cast<const float4*>(&Ab[a_row * HH + k0n + c4 * 4]);
            }
            #pragma unroll
            for (int i = 0; i < 4; i++) {
                int r = b_row + i * 8;
                pb[i] = *reinterpret_cast<const float4*>(&Wb[(k0n + r) * HH + n0 + b_c4 * 4]);
            }
        }

        // ---- compute 32 k-steps ----
        #pragma unroll 8
        for (int k = 0; k < BK; k++) {
            float4 av = *reinterpret_cast<const float4*>(&sAT[k][tm * 4]);
            ulonglong2 b01 = *reinterpret_cast<const ulonglong2*>(&sB[k][tn * 8]);
            ulonglong2 b23 = *reinterpret_cast<const ulonglong2*>(&sB[k][tn * 8 + 4]);
            unsigned long long bb0 = b01.x, bb1 = b01.y, bb2 = b23.x, bb3 = b23.y;
            float am[4] = {av.x, av.y, av.z, av.w};
            #pragma unroll
            for (int m = 0; m < 4; m++) {
                unsigned long long a2;
                PACKDUP(a2, am[m]);
                FMA2(acc[m][0], a2, bb0);
                FMA2(acc[m][1], a2, bb1);
                FMA2(acc[m][2], a2, bb2);
                FMA2(acc[m][3], a2, bb3);
            }
        }
        __syncthreads();

        if (pre) {
            #pragma unroll
            for (int i = 0; i < 2; i++) {
                int c4 = a_c4 + i * 4;
                sAT[c4 * 4 + 0][a_row] = pa[i].x;
                sAT[c4 * 4 + 1][a_row] = pa[i].y;
                sAT[c4 * 4 + 2][a_row] = pa[i].z;
                sAT[c4 * 4 + 3][a_row] = pa[i].w;
            }
            #pragma unroll
            for (int i = 0; i < 4; i++) {
                int r = b_row + i * 8;
                *reinterpret_cast<float4*>(&sB[r][b_c4 * 4]) = pb[i];
            }
            __syncthreads();
        }
    }

    // ---- epilogue ----
    const float* biasE = bias + e * HH;
    const float* tcB   = g_tc + (size_t)b * HH;
    #pragma unroll
    for (int m = 0; m < 4; m++) {
        int row = tm * 4 + m;
        #pragma unroll
        for (int j = 0; j < 4; j++) {
            unsigned lo, hi;
            UNPACK2(lo, hi, acc[m][j]);
            int n = n0 + tn * 8 + j * 2;
            float v0 = __uint_as_float(lo) + biasE[n];
            float v1 = __uint_as_float(hi) + biasE[n + 1];
            if (LAYER == 2) {
                v0 += tcB[n];
                v1 += tcB[n + 1];
                v0 = v0 / (1.0f + expf(-v0));   // swish
                v1 = v1 / (1.0f + expf(-v1));
            }
            *reinterpret_cast<float2*>(&Cb[row * HH + n]) = make_float2(v0, v1);
        }
    }
}

// ---------------------------------------------------------------------------
extern "C" void kernel_launch(void* const* d_in, const int* in_sizes, int n_in,
                              void* d_out, int out_size)
{
    const float* actions   = (const float*)d_in[0];
    const int*   timesteps = (const int*)  d_in[1];
    const int*   cat_ids   = (const int*)  d_in[2];
    const float* W1        = (const float*)d_in[3];
    const float* b1        = (const float*)d_in[4];
    const float* W2        = (const float*)d_in[5];
    const float* b2        = (const float*)d_in[6];
    const float* W3        = (const float*)d_in[7];
    const float* b3        = (const float*)d_in[8];
    float* out = (float*)d_out;

    k1_embed<<<BSZ, 256>>>(actions, timesteps, cat_ids, W1, b1, W2);

    dim3 grid(HH / 128, BSZ);
    gemm64<2><<<grid, 256>>>(W2, b2, cat_ids, nullptr);  // -> g_x2 (swish, +tc)
    gemm64<3><<<grid, 256>>>(W3, b3, cat_ids, out);      // -> d_out
}

// round 4
// speedup vs baseline: 2.1879x; 2.1795x over previous
#include <cuda_runtime.h>
#include <cuda_bf16.h>
#include <cstdint>
#include <math.h>

#define BSZ 256
#define TT  64
#define AA  32
#define HH  512
#define EE  32

// -------- device scratch (allocation-free) --------
__device__ __align__(256) __nv_bfloat16 g_B2[EE][HH][2048]; // [e][n][hi(1024)|lo(1024)]
__device__ __align__(256) __nv_bfloat16 g_B3[EE][HH][1024]; // [e][n][hi(512)|lo(512)]
__device__ __align__(256) __nv_bfloat16 g_A2[BSZ][TT][2048]; // [hi a|tau (1024) | lo a|tau (1024)]
__device__ __align__(256) __nv_bfloat16 g_A3[BSZ][TT][1024]; // [hi(512)|lo(512)]
__device__ int2 g_pairs[160];
__device__ int  g_npairs;

// -------- helpers --------
__device__ __forceinline__ uint32_t smem_u32(const void* p){
    uint32_t a;
    asm("{ .reg .u64 t; cvta.to.shared.u64 t, %1; cvt.u32.u64 %0, t; }" : "=r"(a) : "l"(p));
    return a;
}
__device__ __forceinline__ unsigned pk(__nv_bfloat16 a, __nv_bfloat16 b){
    unsigned short x = *reinterpret_cast<unsigned short*>(&a);
    unsigned short y = *reinterpret_cast<unsigned short*>(&b);
    return (unsigned)x | ((unsigned)y << 16);
}

#define CP_ASYNC16(dst, src) \
    asm volatile("cp.async.cg.shared.global [%0], [%1], 16;" :: "r"(dst), "l"(src))
#define CP_COMMIT() asm volatile("cp.async.commit_group;" ::: "memory")
#define CP_WAIT0()  asm volatile("cp.async.wait_group 0;" ::: "memory")
#define CP_WAIT1()  asm volatile("cp.async.wait_group 1;" ::: "memory")

#define LDSM_X4(r, addr) \
    asm volatile("ldmatrix.sync.aligned.m8n8.x4.shared.b16 {%0,%1,%2,%3}, [%4];" \
        : "=r"((r)[0]), "=r"((r)[1]), "=r"((r)[2]), "=r"((r)[3]) : "r"(addr))

#define MMA16816(d, a, b0, b1) \
    asm volatile("mma.sync.aligned.m16n8k16.row.col.f32.bf16.bf16.f32 " \
        "{%0,%1,%2,%3}, {%4,%5,%6,%7}, {%8,%9}, {%0,%1,%2,%3};" \
        : "+f"((d)[0]), "+f"((d)[1]), "+f"((d)[2]), "+f"((d)[3]) \
        : "r"((a)[0]), "r"((a)[1]), "r"((a)[2]), "r"((a)[3]), "r"(b0), "r"(b1))

// ---------------------------------------------------------------------------
// Weight conversion: W (E,K,512) fp32 -> [E][512][2K] bf16 (transpose, hi|lo)
// ---------------------------------------------------------------------------
template <int K>
__global__ __launch_bounds__(256) void conv_w(const float* __restrict__ W)
{
    __shared__ float sm[32][33];
    const int kt = blockIdx.x, nt = blockIdx.y, e = blockIdx.z;
    const int k0 = kt * 32, n0 = nt * 32;
    const int tid = threadIdx.x;
    #pragma unroll
    for (int i = 0; i < 4; i++) {
        int idx = tid + i * 256;
        int kk = idx >> 5, nn = idx & 31;
        sm[kk][nn] = W[((size_t)e * K + k0 + kk) * HH + n0 + nn];
    }
    __syncthreads();
    const int n = tid >> 3, g = tid & 7;
    __nv_bfloat16 hi[4], lo[4];
    #pragma unroll
    for (int j = 0; j < 4; j++) {
        float x = sm[g * 4 + j][n];
        hi[j] = __float2bfloat16_rn(x);
        lo[j] = __float2bfloat16_rn(x - __bfloat162float(hi[j]));
    }
    __nv_bfloat16* dst = ((K == 1024) ? &g_B2[0][0][0] : &g_B3[0][0][0])
                       + ((size_t)e * HH + n0 + n) * (2 * K) + k0 + g * 4;
    *reinterpret_cast<uint2*>(dst)     = make_uint2(pk(hi[0], hi[1]), pk(hi[2], hi[3]));
    *reinterpret_cast<uint2*>(dst + K) = make_uint2(pk(lo[0], lo[1]), pk(lo[2], lo[3]));
}

// ---------------------------------------------------------------------------
// Pair samples with equal expert (odd counts: duplicate last sample)
// ---------------------------------------------------------------------------
__global__ void k_pairs(const int* __restrict__ cat_ids)
{
    int e = threadIdx.x;  // 32 threads
    int cnt = 0;
    for (int s = 0; s < BSZ; s++) cnt += (cat_ids[s] == e);
    int np = (cnt + 1) >> 1;
    int inc = np;
    for (int d = 1; d < 32; d <<= 1) {
        int v = __shfl_up_sync(0xffffffffu, inc, d);
        if (e >= d) inc += v;
    }
    int off = inc - np;
    if (e == 31) g_npairs = off + np;
    int a = -1, w = off;
    for (int s = 0; s < BSZ; s++) {
        if (cat_ids[s] == e) {
            if (a < 0) a = s;
            else { g_pairs[w++] = make_int2(a, s); a = -1; }
        }
    }
    if (a >= 0) g_pairs[w++] = make_int2(a, a);
}

// ---------------------------------------------------------------------------
// k1: a_emb = actions@W1[e]+b1 -> hi/lo bf16; sinusoidal tau -> hi/lo bf16
// ---------------------------------------------------------------------------
__global__ __launch_bounds__(256) void k1_embed(
    const float* __restrict__ actions, const int* __restrict__ timesteps,
    const int* __restrict__ cat_ids, const float* __restrict__ W1,
    const float* __restrict__ b1)
{
    const int b = blockIdx.x, tid = threadIdx.x;
    const int e = cat_ids[b];
    const float tval = (float)timesteps[b];
    __shared__ float sA[TT][36];

    const float* Ab = actions + (size_t)b * TT * AA;
    #pragma unroll
    for (int i = 0; i < 2; i++) {
        int id = tid + i * 256, row = id >> 3, c4 = id & 7;
        float4 v = *reinterpret_cast<const float4*>(&Ab[row * AA + c4 * 4]);
        *reinterpret_cast<float4*>(&sA[row][c4 * 4]) = v;
    }
    // tau for frequency index tid (half = 256)
    float f = tval * expf(-(float)tid * (9.210340371976184f / 256.0f));
    float sv = sinf(f), cv = cosf(f);
    __nv_bfloat16 sh = __float2bfloat16_rn(sv), ch = __float2bfloat16_rn(cv);
    __nv_bfloat16 sl = __float2bfloat16_rn(sv - __bfloat162float(sh));
    __nv_bfloat16 cl = __float2bfloat16_rn(cv - __bfloat162float(ch));
    unsigned short shu = *reinterpret_cast<unsigned short*>(&sh);
    unsigned short chu = *reinterpret_cast<unsigned short*>(&ch);
    unsigned short slu = *reinterpret_cast<unsigned short*>(&sl);
    unsigned short clu = *reinterpret_cast<unsigned short*>(&cl);
    __syncthreads();

    const int h0 = 2 * tid;
    const float* W1e = W1 + (size_t)e * AA * HH;
    float2 w[AA];
    #pragma unroll
    for (int k = 0; k < AA; k++)
        w[k] = *reinterpret_cast<const float2*>(&W1e[k * HH + h0]);
    const float2 bv = *reinterpret_cast<const float2*>(&b1[e * HH + h0]);

    for (int t = 0; t < TT; t++) {
        float a0 = bv.x, a1 = bv.y;
        #pragma unroll
        for (int k = 0; k < AA; k++) {
            float av = sA[t][k];
            a0 += av * w[k].x; a1 += av * w[k].y;
        }
        __nv_bfloat16 hh0 = __float2bfloat16_rn(a0), hh1 = __float2bfloat16_rn(a1);
        __nv_bfloat16 ll0 = __float2bfloat16_rn(a0 - __bfloat162float(hh0));
        __nv_bfloat16 ll1 = __float2bfloat16_rn(a1 - __bfloat162float(hh1));
        __nv_bfloat16* row = &g_A2[b][t][0];
        *reinterpret_cast<unsigned*>(row + h0)        = pk(hh0, hh1);
        *reinterpret_cast<unsigned*>(row + 1024 + h0) = pk(ll0, ll1);
        *reinterpret_cast<unsigned short*>(row + 512 + tid)  = shu;
        *reinterpret_cast<unsigned short*>(row + 768 + tid)  = chu;
        *reinterpret_cast<unsigned short*>(row + 1536 + tid) = slu;
        *reinterpret_cast<unsigned short*>(row + 1792 + tid) = clu;
    }
}

// ---------------------------------------------------------------------------
// mma.sync GEMM: CTA = (n-chunk 256, sample-pair). M=128, N=256.
// 8 warps (2x4): warp tile 64x64. K-chunks of 64 bf16, 3-stage cp.async.
// Virtual K = 3*KP: term0 hi*hi, term1 Alo*Bhi, term2 Ahi*Blo.
// SMEM per stage: A 16KB + B 32KB = 48KB; 3 stages.
// ---------------------------------------------------------------------------
#define STAGE_BYTES 49152
#define GSMEM (3 * STAGE_BYTES + 128)

template <int LAYER>
__global__ __launch_bounds__(256, 1) void gemm_mma(
    const float* __restrict__ bias, const int* __restrict__ cat_ids,
    float* __restrict__ out)
{
    constexpr int KP  = (LAYER == 2) ? 1024 : 512;
    constexpr int TPC = KP / 64;
    constexpr int NC  = 3 * TPC;

    const int mt_blk = blockIdx.y;
    if (mt_blk >= g_npairs) return;
    const int n0 = blockIdx.x * 256;
    const int2 pr = g_pairs[mt_blk];
    const int s0 = pr.x, s1 = pr.y;
    const int e  = cat_ids[s0];

    extern __shared__ char smem[];
    const uint32_t sb = (smem_u32(smem) + 127) & ~127u;

    const int tid  = threadIdx.x;
    const int wid  = tid >> 5;
    const int lane = tid & 31;
    const int mWarp = (wid >> 2) * 64;   // 0 or 64
    const int nWarp = (wid & 3) * 64;    // 0,64,128,192

    // ---- cp.async source/dest tables ----
    const __nv_bfloat16* aRow[4]; uint32_t dAo[4];
    #pragma unroll
    for (int i = 0; i < 4; i++) {
        int idx = tid + 256 * i;
        int r = idx >> 3, sg = idx & 7;
        int samp = (r < 64) ? s0 : s1;
        aRow[i] = ((LAYER == 2) ? &g_A2[samp][r & 63][0] : &g_A3[samp][r & 63][0]) + sg * 8;
        dAo[i]  = (uint32_t)(r * 128 + ((sg * 16) ^ ((r & 7) * 16)));
    }
    const __nv_bfloat16* bRow[8]; uint32_t dBo[8];
    #pragma unroll
    for (int i = 0; i < 8; i++) {
        int idx = tid + 256 * i;
        int r = idx >> 3, sg = idx & 7;
        bRow[i] = ((LAYER == 2) ? &g_B2[e][n0 + r][0] : &g_B3[e][n0 + r][0]) + sg * 8;
        dBo[i]  = (uint32_t)(16384 + r * 128 + ((sg * 16) ^ ((r & 7) * 16)));
    }

    auto issue = [&](int c) {
        int st = c % 3;
        int term = c / TPC;
        int pkk  = (c % TPC) * 64;
        int ao = pkk + ((term == 1) ? KP : 0);
        int bo = pkk + ((term == 2) ? KP : 0);
        uint32_t sof = sb + (uint32_t)st * STAGE_BYTES;
        #pragma unroll
        for (int i = 0; i < 4; i++) CP_ASYNC16(sof + dAo[i], aRow[i] + ao);
        #pragma unroll
        for (int i = 0; i < 8; i++) CP_ASYNC16(sof + dBo[i], bRow[i] + bo);
        CP_COMMIT();
    };

    // ---- ldmatrix lane addressing (SW128-style swizzle) ----
    const uint32_t maskk = (lane & 7) * 16;
    const uint32_t aRowB = (uint32_t)(mWarp + (lane & 7) + ((lane & 8) ? 8 : 0)) * 128;
    const uint32_t kextA = (lane & 16) ? 16 : 0;
    const uint32_t bRowB = (uint32_t)(16384 + (nWarp + (lane & 7) + ((lane & 16) ? 8 : 0)) * 128);
    const uint32_t kextB = (lane & 8) ? 16 : 0;

    float acc[4][8][4];
    #pragma unroll
    for (int m = 0; m < 4; m++)
        #pragma unroll
        for (int j = 0; j < 8; j++)
            #pragma unroll
            for (int q = 0; q < 4; q++) acc[m][j][q] = 0.f;

    issue(0); issue(1);

    for (int c = 0; c < NC; c++) {
        if (c == NC - 1) { CP_WAIT0(); } else { CP_WAIT1(); }
        __syncthreads();
        if (c + 2 < NC) issue(c + 2);

        const uint32_t stb = sb + (uint32_t)(c % 3) * STAGE_BYTES;
        #pragma unroll
        for (int ks = 0; ks < 4; ks++) {
            uint32_t a[4][4], b[4][4];
            const uint32_t kA = (uint32_t)(ks * 32 + kextA) ^ maskk;
            const uint32_t kB = (uint32_t)(ks * 32 + kextB) ^ maskk;
            #pragma unroll
            for (int m = 0; m < 4; m++)
                LDSM_X4(a[m], stb + aRowB + m * 2048 + kA);
            #pragma unroll
            for (int nt = 0; nt < 4; nt++)
                LDSM_X4(b[nt], stb + bRowB + nt * 2048 + kB);
            #pragma unroll
            for (int m = 0; m < 4; m++)
                #pragma unroll
                for (int j = 0; j < 8; j++)
                    MMA16816(acc[m][j], a[m], b[j >> 1][(j & 1) * 2], b[j >> 1][(j & 1) * 2 + 1]);
        }
    }

    // ---- epilogue ----
    const float* biasE = bias + e * HH;
    const int sampW = (mWarp < 64) ? s0 : s1;
    #pragma unroll
    for (int m = 0; m < 4; m++) {
        int rloc = mWarp + m * 16 + (lane >> 2);
        int t0 = rloc & 63, t1 = (rloc + 8) & 63;
        #pragma unroll
        for (int j = 0; j < 8; j++) {
            int cidx = n0 + nWarp + j * 8 + (lane & 3) * 2;
            float2 bv = *reinterpret_cast<const float2*>(&biasE[cidx]);
            float v00 = acc[m][j][0] + bv.x, v01 = acc[m][j][1] + bv.y;
            float v10 = acc[m][j][2] + bv.x, v11 = acc[m][j][3] + bv.y;
            if (LAYER == 2) {
                v00 = v00 * (1.f / (1.f + expf(-v00)));
                v01 = v01 * (1.f / (1.f + expf(-v01)));
                v10 = v10 * (1.f / (1.f + expf(-v10)));
                v11 = v11 * (1.f / (1.f + expf(-v11)));
                __nv_bfloat16 h00 = __float2bfloat16_rn(v00), h01 = __float2bfloat16_rn(v01);
                __nv_bfloat16 h10 = __float2bfloat16_rn(v10), h11 = __float2bfloat16_rn(v11);
                __nv_bfloat16 l00 = __float2bfloat16_rn(v00 - __bfloat162float(h00));
                __nv_bfloat16 l01 = __float2bfloat16_rn(v01 - __bfloat162float(h01));
                __nv_bfloat16 l10 = __float2bfloat16_rn(v10 - __bfloat162float(h10));
                __nv_bfloat16 l11 = __float2bfloat16_rn(v11 - __bfloat162float(h11));
                __nv_bfloat16* p0 = &g_A3[sampW][t0][cidx];
                __nv_bfloat16* p1 = &g_A3[sampW][t1][cidx];
                *reinterpret_cast<unsigned*>(p0)       = pk(h00, h01);
                *reinterpret_cast<unsigned*>(p0 + 512) = pk(l00, l01);
                *reinterpret_cast<unsigned*>(p1)       = pk(h10, h11);
                *reinterpret_cast<unsigned*>(p1 + 512) = pk(l10, l11);
            } else {
                float* p0 = out + ((size_t)sampW * TT + t0) * HH + cidx;
                float* p1 = out + ((size_t)sampW * TT + t1) * HH + cidx;
                *reinterpret_cast<float2*>(p0) = make_float2(v00, v01);
                *reinterpret_cast<float2*>(p1) = make_float2(v10, v11);
            }
        }
    }
}

// ---------------------------------------------------------------------------
extern "C" void kernel_launch(void* const* d_in, const int* in_sizes, int n_in,
                              void* d_out, int out_size)
{
    const float* actions   = (const float*)d_in[0];
    const int*   timesteps = (const int*)  d_in[1];
    const int*   cat_ids   = (const int*)  d_in[2];
    const float* W1        = (const float*)d_in[3];
    const float* b1        = (const float*)d_in[4];
    const float* W2        = (const float*)d_in[5];
    const float* b2        = (const float*)d_in[6];
    const float* W3        = (const float*)d_in[7];
    const float* b3        = (const float*)d_in[8];
    float* out = (float*)d_out;

    cudaFuncSetAttribute(gemm_mma<2>, cudaFuncAttributeMaxDynamicSharedMemorySize, GSMEM);
    cudaFuncSetAttribute(gemm_mma<3>, cudaFuncAttributeMaxDynamicSharedMemorySize, GSMEM);

    conv_w<1024><<<dim3(32, 16, EE), 256>>>(W2);
    conv_w<512> <<<dim3(16, 16, EE), 256>>>(W3);
    k_pairs<<<1, 32>>>(cat_ids);
    k1_embed<<<BSZ, 256>>>(actions, timesteps, cat_ids, W1, b1);

    gemm_mma<2><<<dim3(2, 144), 256, GSMEM>>>(b2, cat_ids, nullptr);
    gemm_mma<3><<<dim3(2, 144), 256, GSMEM>>>(b3, cat_ids, out);
}

// round 6
// speedup vs baseline: 2.3934x; 1.0939x over previous
#include <cuda_runtime.h>
#include <cuda_bf16.h>
#include <cstdint>
#include <math.h>

#define BSZ 256
#define TT  64
#define AA  32
#define HH  512
#define EE  32

// -------- device scratch (allocation-free) --------
__device__ __align__(256) __nv_bfloat16 g_B2[EE][HH][2048]; // [e][n][hi(1024)|lo(1024)]
__device__ __align__(256) __nv_bfloat16 g_B3[EE][HH][1024]; // [e][n][hi(512)|lo(512)]
__device__ __align__(256) __nv_bfloat16 g_A2[BSZ][TT][2048]; // [hi a|tau (1024) | lo a|tau (1024)]
__device__ __align__(256) __nv_bfloat16 g_A3[BSZ][TT][1024]; // [hi(512)|lo(512)]
__device__ int2 g_pairs[160];
__device__ int  g_npairs;

// -------- helpers --------
__device__ __forceinline__ uint32_t smem_u32(const void* p){
    uint32_t a;
    asm("{ .reg .u64 t; cvta.to.shared.u64 t, %1; cvt.u32.u64 %0, t; }" : "=r"(a) : "l"(p));
    return a;
}
__device__ __forceinline__ unsigned pk(__nv_bfloat16 a, __nv_bfloat16 b){
    unsigned short x = *reinterpret_cast<unsigned short*>(&a);
    unsigned short y = *reinterpret_cast<unsigned short*>(&b);
    return (unsigned)x | ((unsigned)y << 16);
}

#define CP_ASYNC16(dst, src) \
    asm volatile("cp.async.cg.shared.global [%0], [%1], 16;" :: "r"(dst), "l"(src))
#define CP_COMMIT() asm volatile("cp.async.commit_group;" ::: "memory")
#define CP_WAIT0()  asm volatile("cp.async.wait_group 0;" ::: "memory")
#define CP_WAIT1()  asm volatile("cp.async.wait_group 1;" ::: "memory")

#define LDSM_X4(r, addr) \
    asm volatile("ldmatrix.sync.aligned.m8n8.x4.shared.b16 {%0,%1,%2,%3}, [%4];" \
        : "=r"((r)[0]), "=r"((r)[1]), "=r"((r)[2]), "=r"((r)[3]) : "r"(addr))

#define MMA16816(d, a, b0, b1) \
    asm volatile("mma.sync.aligned.m16n8k16.row.col.f32.bf16.bf16.f32 " \
        "{%0,%1,%2,%3}, {%4,%5,%6,%7}, {%8,%9}, {%0,%1,%2,%3};" \
        : "+f"((d)[0]), "+f"((d)[1]), "+f"((d)[2]), "+f"((d)[3]) \
        : "r"((a)[0]), "r"((a)[1]), "r"((a)[2]), "r"((a)[3]), "r"(b0), "r"(b1))

// ---------------------------------------------------------------------------
// Weight conversion: W (E,K,512) fp32 -> [E][512][2K] bf16 (transpose, hi|lo)
// ---------------------------------------------------------------------------
template <int K>
__global__ __launch_bounds__(256) void conv_w(const float* __restrict__ W)
{
    __shared__ float sm[32][33];
    const int kt = blockIdx.x, nt = blockIdx.y, e = blockIdx.z;
    const int k0 = kt * 32, n0 = nt * 32;
    const int tid = threadIdx.x;
    #pragma unroll
    for (int i = 0; i < 4; i++) {
        int idx = tid + i * 256;
        int kk = idx >> 5, nn = idx & 31;
        sm[kk][nn] = W[((size_t)e * K + k0 + kk) * HH + n0 + nn];
    }
    __syncthreads();
    const int n = tid >> 3, g = tid & 7;
    __nv_bfloat16 hi[4], lo[4];
    #pragma unroll
    for (int j = 0; j < 4; j++) {
        float x = sm[g * 4 + j][n];
        hi[j] = __float2bfloat16_rn(x);
        lo[j] = __float2bfloat16_rn(x - __bfloat162float(hi[j]));
    }
    __nv_bfloat16* dst = ((K == 1024) ? &g_B2[0][0][0] : &g_B3[0][0][0])
                       + ((size_t)e * HH + n0 + n) * (2 * K) + k0 + g * 4;
    *reinterpret_cast<uint2*>(dst)     = make_uint2(pk(hi[0], hi[1]), pk(hi[2], hi[3]));
    *reinterpret_cast<uint2*>(dst + K) = make_uint2(pk(lo[0], lo[1]), pk(lo[2], lo[3]));
}

// ---------------------------------------------------------------------------
// Pair samples with equal expert (odd counts: duplicate last sample)
// ---------------------------------------------------------------------------
__global__ void k_pairs(const int* __restrict__ cat_ids)
{
    int e = threadIdx.x;  // 32 threads
    int cnt = 0;
    for (int s = 0; s < BSZ; s++) cnt += (cat_ids[s] == e);
    int np = (cnt + 1) >> 1;
    int inc = np;
    for (int d = 1; d < 32; d <<= 1) {
        int v = __shfl_up_sync(0xffffffffu, inc, d);
        if (e >= d) inc += v;
    }
    int off = inc - np;
    if (e == 31) g_npairs = off + np;
    int a = -1, w = off;
    for (int s = 0; s < BSZ; s++) {
        if (cat_ids[s] == e) {
            if (a < 0) a = s;
            else { g_pairs[w++] = make_int2(a, s); a = -1; }
        }
    }
    if (a >= 0) g_pairs[w++] = make_int2(a, a);
}

// ---------------------------------------------------------------------------
// k1: a_emb = actions@W1[e]+b1 -> hi/lo bf16; sinusoidal tau -> hi/lo bf16
// grid (BSZ, 2): each CTA handles 32 of the 64 timesteps.
// ---------------------------------------------------------------------------
__global__ __launch_bounds__(256) void k1_embed(
    const float* __restrict__ actions, const int* __restrict__ timesteps,
    const int* __restrict__ cat_ids, const float* __restrict__ W1,
    const float* __restrict__ b1)
{
    const int b = blockIdx.x, tid = threadIdx.x;
    const int tbase = blockIdx.y * 32;
    const int e = cat_ids[b];
    const float tval = (float)timesteps[b];
    __shared__ float sA[32][36];

    const float* Ab = actions + ((size_t)b * TT + tbase) * AA;
    {
        int row = tid >> 3, c4 = tid & 7;
        float4 v = *reinterpret_cast<const float4*>(&Ab[row * AA + c4 * 4]);
        *reinterpret_cast<float4*>(&sA[row][c4 * 4]) = v;
    }
    // tau for frequency index tid (half = 256); both y-blocks write same values
    float f = tval * expf(-(float)tid * (9.210340371976184f / 256.0f));
    float sv = sinf(f), cv = cosf(f);
    __nv_bfloat16 sh = __float2bfloat16_rn(sv), ch = __float2bfloat16_rn(cv);
    __nv_bfloat16 sl = __float2bfloat16_rn(sv - __bfloat162float(sh));
    __nv_bfloat16 cl = __float2bfloat16_rn(cv - __bfloat162float(ch));
    unsigned short shu = *reinterpret_cast<unsigned short*>(&sh);
    unsigned short chu = *reinterpret_cast<unsigned short*>(&ch);
    unsigned short slu = *reinterpret_cast<unsigned short*>(&sl);
    unsigned short clu = *reinterpret_cast<unsigned short*>(&cl);
    __syncthreads();

    const int h0 = 2 * tid;
    const float* W1e = W1 + (size_t)e * AA * HH;
    float2 w[AA];
    #pragma unroll
    for (int k = 0; k < AA; k++)
        w[k] = *reinterpret_cast<const float2*>(&W1e[k * HH + h0]);
    const float2 bv = *reinterpret_cast<const float2*>(&b1[e * HH + h0]);

    for (int tl = 0; tl < 32; tl++) {
        float a0 = bv.x, a1 = bv.y;
        #pragma unroll
        for (int k = 0; k < AA; k++) {
            float av = sA[tl][k];
            a0 += av * w[k].x; a1 += av * w[k].y;
        }
        __nv_bfloat16 hh0 = __float2bfloat16_rn(a0), hh1 = __float2bfloat16_rn(a1);
        __nv_bfloat16 ll0 = __float2bfloat16_rn(a0 - __bfloat162float(hh0));
        __nv_bfloat16 ll1 = __float2bfloat16_rn(a1 - __bfloat162float(hh1));
        __nv_bfloat16* row = &g_A2[b][tbase + tl][0];
        *reinterpret_cast<unsigned*>(row + h0)        = pk(hh0, hh1);
        *reinterpret_cast<unsigned*>(row + 1024 + h0) = pk(ll0, ll1);
        *reinterpret_cast<unsigned short*>(row + 512 + tid)  = shu;
        *reinterpret_cast<unsigned short*>(row + 768 + tid)  = chu;
        *reinterpret_cast<unsigned short*>(row + 1536 + tid) = slu;
        *reinterpret_cast<unsigned short*>(row + 1792 + tid) = clu;
    }
}

// ---------------------------------------------------------------------------
// mma.sync GEMM, fused 3-term: per physical K64 chunk load Ahi/Alo/Bhi/Blo
// once and issue hi*hi + lo*hi + hi*lo. CTA = (n-chunk 256, sample pair).
// M=128, N=256, 8 warps (2x4), warp tile 64x64. 2-stage cp.async.
// Stage layout: Ahi@0 (16K) | Alo@16K | Bhi@32K (32K) | Blo@64K (32K) = 96KB.
// ---------------------------------------------------------------------------
#define STAGE_BYTES 98304
#define GSMEM (2 * STAGE_BYTES + 1024)

template <int LAYER>
__global__ __launch_bounds__(256, 1) void gemm_mma(
    const float* __restrict__ bias, const int* __restrict__ cat_ids,
    float* __restrict__ out)
{
    constexpr int KP  = (LAYER == 2) ? 1024 : 512;
    constexpr int TPC = KP / 64;   // physical chunks

    const int mt_blk = blockIdx.y;
    if (mt_blk >= g_npairs) return;
    const int n0 = blockIdx.x * 256;
    const int2 pr = g_pairs[mt_blk];
    const int s0 = pr.x, s1 = pr.y;
    const int e  = cat_ids[s0];

    extern __shared__ char smem[];
    const uint32_t sb = (smem_u32(smem) + 127) & ~127u;

    const int tid  = threadIdx.x;
    const int wid  = tid >> 5;
    const int lane = tid & 31;
    const int mWarp = (wid >> 2) * 64;   // 0 or 64
    const int nWarp = (wid & 3) * 64;    // 0,64,128,192

    // ---- cp.async source/dest tables ----
    const __nv_bfloat16* aRow[4]; uint32_t dAo[4];
    #pragma unroll
    for (int i = 0; i < 4; i++) {
        int idx = tid + 256 * i;
        int r = idx >> 3, sg = idx & 7;
        int samp = (r < 64) ? s0 : s1;
        aRow[i] = ((LAYER == 2) ? &g_A2[samp][r & 63][0] : &g_A3[samp][r & 63][0]) + sg * 8;
        dAo[i]  = (uint32_t)(r * 128 + ((sg * 16) ^ ((r & 7) * 16)));
    }
    const __nv_bfloat16* bRow[8]; uint32_t dBo[8];
    #pragma unroll
    for (int i = 0; i < 8; i++) {
        int idx = tid + 256 * i;
        int r = idx >> 3, sg = idx & 7;
        bRow[i] = ((LAYER == 2) ? &g_B2[e][n0 + r][0] : &g_B3[e][n0 + r][0]) + sg * 8;
        dBo[i]  = (uint32_t)(r * 128 + ((sg * 16) ^ ((r & 7) * 16)));
    }

    auto issue = [&](int c) {
        int pkk = c * 64;
        uint32_t sof = sb + (uint32_t)(c & 1) * STAGE_BYTES;
        #pragma unroll
        for (int i = 0; i < 4; i++) {
            CP_ASYNC16(sof + dAo[i],         aRow[i] + pkk);       // Ahi
            CP_ASYNC16(sof + 16384 + dAo[i], aRow[i] + KP + pkk);  // Alo
        }
        #pragma unroll
        for (int i = 0; i < 8; i++) {
            CP_ASYNC16(sof + 32768 + dBo[i], bRow[i] + pkk);       // Bhi
            CP_ASYNC16(sof + 65536 + dBo[i], bRow[i] + KP + pkk);  // Blo
        }
        CP_COMMIT();
    };

    // ---- ldmatrix lane addressing (SW128-style swizzle) ----
    const uint32_t maskk = (lane & 7) * 16;
    const uint32_t aRowB = (uint32_t)(mWarp + (lane & 7) + ((lane & 8) ? 8 : 0)) * 128;
    const uint32_t kextA = (lane & 16) ? 16 : 0;
    const uint32_t bRowB = (uint32_t)((nWarp + (lane & 7) + ((lane & 16) ? 8 : 0)) * 128);
    const uint32_t kextB = (lane & 8) ? 16 : 0;

    float acc[4][8][4];
    #pragma unroll
    for (int m = 0; m < 4; m++)
        #pragma unroll
        for (int j = 0; j < 8; j++)
            #pragma unroll
            for (int q = 0; q < 4; q++) acc[m][j][q] = 0.f;

    issue(0);

    for (int c = 0; c < TPC; c++) {
        __syncthreads();   // prev compute done before overwriting old stage
        if (c + 1 < TPC) { issue(c + 1); CP_WAIT1(); } else { CP_WAIT0(); }
        __syncthreads();

        const uint32_t stb = sb + (uint32_t)(c & 1) * STAGE_BYTES;
        #pragma unroll
        for (int ks = 0; ks < 4; ks++) {
            const uint32_t kA = (uint32_t)(ks * 32 + kextA) ^ maskk;
            const uint32_t kB = (uint32_t)(ks * 32 + kextB) ^ maskk;
            uint32_t a[4][4], b[4][4], c2[4][4];
            // Ahi, Bhi
            #pragma unroll
            for (int m = 0; m < 4; m++)
                LDSM_X4(a[m], stb + aRowB + m * 2048 + kA);
            #pragma unroll
            for (int nt = 0; nt < 4; nt++)
                LDSM_X4(b[nt], stb + 32768 + bRowB + nt * 2048 + kB);
            #pragma unroll
            for (int m = 0; m < 4; m++)
                #pragma unroll
                for (int j = 0; j < 8; j++)
                    MMA16816(acc[m][j], a[m], b[j >> 1][(j & 1) * 2], b[j >> 1][(j & 1) * 2 + 1]);
            // Alo * Bhi
            #pragma unroll
            for (int m = 0; m < 4; m++)
                LDSM_X4(c2[m], stb + 16384 + aRowB + m * 2048 + kA);
            #pragma unroll
            for (int m = 0; m < 4; m++)
                #pragma unroll
                for (int j = 0; j < 8; j++)
                    MMA16816(acc[m][j], c2[m], b[j >> 1][(j & 1) * 2], b[j >> 1][(j & 1) * 2 + 1]);
            // Ahi * Blo (reuse c2 for Blo)
            #pragma unroll
            for (int nt = 0; nt < 4; nt++)
                LDSM_X4(c2[nt], stb + 65536 + bRowB + nt * 2048 + kB);
            #pragma unroll
            for (int m = 0; m < 4; m++)
                #pragma unroll
                for (int j = 0; j < 8; j++)
                    MMA16816(acc[m][j], a[m], c2[j >> 1][(j & 1) * 2], c2[j >> 1][(j & 1) * 2 + 1]);
        }
    }

    // ---- epilogue ----
    const float* biasE = bias + e * HH;
    const int sampW = (mWarp < 64) ? s0 : s1;
    #pragma unroll
    for (int m = 0; m < 4; m++) {
        int rloc = mWarp + m * 16 + (lane >> 2);
        int t0 = rloc & 63, t1 = (rloc + 8) & 63;
        #pragma unroll
        for (int j = 0; j < 8; j++) {
            int cidx = n0 + nWarp + j * 8 + (lane & 3) * 2;
            float2 bv = *reinterpret_cast<const float2*>(&biasE[cidx]);
            float v00 = acc[m][j][0] + bv.x, v01 = acc[m][j][1] + bv.y;
            float v10 = acc[m][j][2] + bv.x, v11 = acc[m][j][3] + bv.y;
            if (LAYER == 2) {
                v00 = v00 * (1.f / (1.f + expf(-v00)));
                v01 = v01 * (1.f / (1.f + expf(-v01)));
                v10 = v10 * (1.f / (1.f + expf(-v10)));
                v11 = v11 * (1.f / (1.f + expf(-v11)));
                __nv_bfloat16 h00 = __float2bfloat16_rn(v00), h01 = __float2bfloat16_rn(v01);
                __nv_bfloat16 h10 = __float2bfloat16_rn(v10), h11 = __float2bfloat16_rn(v11);
                __nv_bfloat16 l00 = __float2bfloat16_rn(v00 - __bfloat162float(h00));
                __nv_bfloat16 l01 = __float2bfloat16_rn(v01 - __bfloat162float(h01));
                __nv_bfloat16 l10 = __float2bfloat16_rn(v10 - __bfloat162float(h10));
                __nv_bfloat16 l11 = __float2bfloat16_rn(v11 - __bfloat162float(h11));
                __nv_bfloat16* p0 = &g_A3[sampW][t0][cidx];
                __nv_bfloat16* p1 = &g_A3[sampW][t1][cidx];
                *reinterpret_cast<unsigned*>(p0)       = pk(h00, h01);
                *reinterpret_cast<unsigned*>(p0 + 512) = pk(l00, l01);
                *reinterpret_cast<unsigned*>(p1)       = pk(h10, h11);
                *reinterpret_cast<unsigned*>(p1 + 512) = pk(l10, l11);
            } else {
                float* p0 = out + ((size_t)sampW * TT + t0) * HH + cidx;
                float* p1 = out + ((size_t)sampW * TT + t1) * HH + cidx;
                *reinterpret_cast<float2*>(p0) = make_float2(v00, v01);
                *reinterpret_cast<float2*>(p1) = make_float2(v10, v11);
            }
        }
    }
}

// ---------------------------------------------------------------------------
extern "C" void kernel_launch(void* const* d_in, const int* in_sizes, int n_in,
                              void* d_out, int out_size)
{
    const float* actions   = (const float*)d_in[0];
    const int*   timesteps = (const int*)  d_in[1];
    const int*   cat_ids   = (const int*)  d_in[2];
    const float* W1        = (const float*)d_in[3];
    const float* b1        = (const float*)d_in[4];
    const float* W2        = (const float*)d_in[5];
    const float* b2        = (const float*)d_in[6];
    const float* W3        = (const float*)d_in[7];
    const float* b3        = (const float*)d_in[8];
    float* out = (float*)d_out;

    cudaFuncSetAttribute(gemm_mma<2>, cudaFuncAttributeMaxDynamicSharedMemorySize, GSMEM);
    cudaFuncSetAttribute(gemm_mma<3>, cudaFuncAttributeMaxDynamicSharedMemorySize, GSMEM);

    conv_w<1024><<<dim3(32, 16, EE), 256>>>(W2);
    conv_w<512> <<<dim3(16, 16, EE), 256>>>(W3);
    k_pairs<<<1, 32>>>(cat_ids);
    k1_embed<<<dim3(BSZ, 2), 256>>>(actions, timesteps, cat_ids, W1, b1);

    gemm_mma<2><<<dim3(2, 144), 256, GSMEM>>>(b2, cat_ids, nullptr);
    gemm_mma<3><<<dim3(2, 144), 256, GSMEM>>>(b3, cat_ids, out);
}